// round 14
// baseline (speedup 1.0000x reference)
#include <cuda_runtime.h>
#include <math.h>
#include <stdint.h>

#define BB 32
#define SS 512
#define DD 512
#define HH 8
#define DHH 64
#define TT (BB*SS)   // 16384 tokens
#define NBH (BB*HH)  // 256

// ---- scratch (__device__ globals; no dynamic alloc) ----
__device__ float g_ah[(size_t)1024 * 64 * 128];
__device__ float g_al[(size_t)1024 * 64 * 128];
__device__ float g_bh[3][(size_t)64 * 64 * 64];
__device__ float g_bl[3][(size_t)64 * 64 * 64];
// Q split A-frag planes: [bh(256)][qf(32)][kf(8)][lane(32)][e(4)]
__device__ float gQh[(size_t)NBH * 32 * 8 * 128];
__device__ float gQl[(size_t)NBH * 32 * 8 * 128];
// K split B-frag planes (n = key): [bh][nf(64)][kf(8)][lane(32)][e(2)]
__device__ float gKh[(size_t)NBH * 64 * 8 * 64];
__device__ float gKl[(size_t)NBH * 64 * 8 * 64];
// V hi-only B-frags (n = dh, k = key): [bh][kf(64)][nf(8)][lane(32)][e(2)]
__device__ float gVh[(size_t)NBH * 64 * 8 * 64];

// output layout: [ ctx0: B*D ][ ctx: B*S*D ][ probs: B*H*S*S ]
#define OUT_CTX   ((size_t)BB * DD)
#define OUT_PROBS (OUT_CTX + (size_t)BB * SS * DD)

// ============================================================
// tf32 split + mma helpers
// ============================================================
__device__ __forceinline__ float2 tf32_split(float x) {
    uint32_t hb;
    asm("cvt.rna.tf32.f32 %0, %1;" : "=r"(hb) : "f"(x));
    float hf = __uint_as_float(hb);
    float lo = x - hf;
    uint32_t lb;
    asm("cvt.rna.tf32.f32 %0, %1;" : "=r"(lb) : "f"(lo));
    return make_float2(hf, __uint_as_float(lb));
}

__device__ __forceinline__ void mma_tf32(float* c,
        uint32_t a0, uint32_t a1, uint32_t a2, uint32_t a3,
        uint32_t b0, uint32_t b1) {
    asm("mma.sync.aligned.m16n8k8.row.col.f32.tf32.tf32.f32 "
        "{%0,%1,%2,%3}, {%4,%5,%6,%7}, {%8,%9}, {%0,%1,%2,%3};"
        : "+f"(c[0]), "+f"(c[1]), "+f"(c[2]), "+f"(c[3])
        : "r"(a0), "r"(a1), "r"(a2), "r"(a3), "r"(b0), "r"(b1));
}

__device__ __forceinline__ void mma3_f(float* c, float4 ah, float4 al,
                                       float2 bhv, float2 blv) {
    uint32_t a0 = __float_as_uint(ah.x), a1 = __float_as_uint(ah.y);
    uint32_t a2 = __float_as_uint(ah.z), a3 = __float_as_uint(ah.w);
    uint32_t l0 = __float_as_uint(al.x), l1 = __float_as_uint(al.y);
    uint32_t l2 = __float_as_uint(al.z), l3 = __float_as_uint(al.w);
    uint32_t b0 = __float_as_uint(bhv.x), b1 = __float_as_uint(bhv.y);
    uint32_t c0 = __float_as_uint(blv.x), c1 = __float_as_uint(blv.y);
    mma_tf32(c, a0, a1, a2, a3, b0, b1);
    mma_tf32(c, a0, a1, a2, a3, c0, c1);
    mma_tf32(c, l0, l1, l2, l3, b0, b1);
}

// 1xTF32: c += Ah*Bh
__device__ __forceinline__ void mma1_f(float* c, float4 ah, float2 bhv) {
    mma_tf32(c, __float_as_uint(ah.x), __float_as_uint(ah.y),
                __float_as_uint(ah.z), __float_as_uint(ah.w),
                __float_as_uint(bhv.x), __float_as_uint(bhv.y));
}

__device__ __forceinline__ void cp16(float* smem_dst, const float* gsrc) {
    uint32_t s = (uint32_t)__cvta_generic_to_shared(smem_dst);
    asm volatile("cp.async.ca.shared.global [%0], [%1], 16;" :: "r"(s), "l"(gsrc));
}
__device__ __forceinline__ void cp_commit() {
    asm volatile("cp.async.commit_group;");
}
__device__ __forceinline__ void cp_wait1() {
    asm volatile("cp.async.wait_group 1;");
}
__device__ __forceinline__ void cp_wait0() {
    asm volatile("cp.async.wait_group 0;");
}

// ============================================================
// Kernel 1: embed + pos + LayerNorm -> split tiled h planes
// ============================================================
#define EMB_SMEM (2 * 16 * 512 * 4)

__global__ void __launch_bounds__(256) embed_ln_kernel(
        const int* __restrict__ x_seq,
        const float* __restrict__ word_emb,
        const float* __restrict__ pos_emb,
        const float* __restrict__ ln_w,
        const float* __restrict__ ln_b) {
    extern __shared__ float es[];
    float* shi = es;
    float* slo = es + 8192;

    int rb   = blockIdx.x;
    int tid  = threadIdx.x;
    int w    = tid >> 5, lane = tid & 31;
    int rloc = 2 * w + (lane >> 4);
    int li   = lane & 15;
    int row  = rb * 16 + rloc;
    int s    = row & (SS - 1);
    int x    = x_seq[row];
    const float* we = word_emb + (size_t)x * DD;
    const float* pe = pos_emb  + (size_t)s * DD;

    float v[32];
    float sum = 0.f;
#pragma unroll
    for (int q = 0; q < 8; q++) {
        int c = li * 32 + q * 4;
        float4 a = *(const float4*)&we[c];
        float4 b = *(const float4*)&pe[c];
        v[q*4+0] = a.x + b.x; v[q*4+1] = a.y + b.y;
        v[q*4+2] = a.z + b.z; v[q*4+3] = a.w + b.w;
        sum += v[q*4+0] + v[q*4+1] + v[q*4+2] + v[q*4+3];
    }
#pragma unroll
    for (int o = 8; o > 0; o >>= 1) sum += __shfl_xor_sync(~0u, sum, o);
    float mu = sum * (1.0f / DD);
    float sq = 0.f;
#pragma unroll
    for (int q = 0; q < 32; q++) { float d = v[q] - mu; sq += d * d; }
#pragma unroll
    for (int o = 8; o > 0; o >>= 1) sq += __shfl_xor_sync(~0u, sq, o);
    float rstd = rsqrtf(sq * (1.0f / DD) + 1e-5f);

    int g  = rloc & 7, hh_ = rloc >> 3;
#pragma unroll
    for (int q = 0; q < 32; q++) {
        int c = li * 32 + q;
        float o = (v[q] - mu) * rstd * ln_w[c] + ln_b[c];
        float2 sp = tf32_split(o);
        int kb = c >> 3, tig = c & 3, ch = (c >> 2) & 1;
        int ta = (kb * 32 + g * 4 + tig) * 4 + hh_ + 2 * ch;
        shi[ta] = sp.x;
        slo[ta] = sp.y;
    }
    __syncthreads();
    size_t base = (size_t)rb * 8192;
#pragma unroll
    for (int r = 0; r < 8; r++) {
        int i = (tid + r * 256) * 4;
        *(float4*)&g_ah[base + i] = *(const float4*)&shi[i];
        *(float4*)&g_al[base + i] = *(const float4*)&slo[i];
    }
}

// ============================================================
// Kernel 1b: split+tile weights (one-shot)
// ============================================================
__global__ void split_w_kernel(const float* __restrict__ wq,
                               const float* __restrict__ wk,
                               const float* __restrict__ wv) {
    int idx = blockIdx.x * 256 + threadIdx.x;
    int z = idx >> 18;
    int rem = idx & ((1 << 18) - 1);
    int n = rem >> 9, k = rem & 511;
    const float* W = (z == 0) ? wq : (z == 1) ? wk : wv;
    float2 sp = tf32_split(W[(size_t)n * DD + k]);
    int cb = n >> 3, kb = k >> 3, g = n & 7, tig = k & 3, e = (k >> 2) & 1;
    size_t a = ((size_t)(cb * 64 + kb) * 32 + g * 4 + tig) * 2 + e;
    g_bh[z][a] = sp.x;
    g_bl[z][a] = sp.y;
}

// ============================================================
// Kernel 2: QKV GEMM — 3-stage cp.async, ONE sync per chunk
// ============================================================
#define QKV_SMEM (3 * 8192 * 4)   // 96KB; 2 CTAs/SM = 192KB

__global__ void __launch_bounds__(256, 2) qkv_mma_kernel(
        const float* __restrict__ bq, const float* __restrict__ bk,
        const float* __restrict__ bv) {
    const float* bias;
    int z = blockIdx.z;
    bias = (z == 0) ? bq : (z == 1) ? bk : bv;
    const float* Bh = g_bh[z];
    const float* Bl = g_bl[z];

    extern __shared__ float smem[];
    int tid  = threadIdx.x;
    int warp = tid >> 5, lane = tid & 31;
    int wm = warp & 1, wn = warp >> 1;
    int rb0 = blockIdx.x * 8;
    int cb0 = blockIdx.y * 16;

    float acc[4][4][4] = {};

    auto copy_chunk = [&](float* st, int kc) {
#pragma unroll
        for (int r = 0; r < 2; r++) {
            int f = (tid + r * 256) * 4;
            int i = f >> 8, j = (f >> 7) & 1, t = f & 127;
            size_t src = ((size_t)(rb0 + i) * 64 + kc * 2 + j) * 128 + t;
            cp16(&st[f],        &g_ah[src]);
            cp16(&st[2048 + f], &g_al[src]);
        }
#pragma unroll
        for (int r = 0; r < 2; r++) {
            int f = (tid + r * 256) * 4;
            int i = f >> 7, j = (f >> 6) & 1, t = f & 63;
            size_t src = ((size_t)(cb0 + i) * 64 + kc * 2 + j) * 64 + t;
            cp16(&st[4096 + f], &Bh[src]);
            cp16(&st[6144 + f], &Bl[src]);
        }
    };

    copy_chunk(smem, 0);          cp_commit();
    copy_chunk(smem + 8192, 1);   cp_commit();

    for (int kc = 0; kc < 32; kc++) {
        float* cur = smem + (kc % 3) * 8192;
        if (kc < 31) cp_wait1(); else cp_wait0();
        __syncthreads();
        if (kc + 2 < 32) {
            copy_chunk(smem + ((kc + 2) % 3) * 8192, kc + 2);
            cp_commit();
        }

#pragma unroll
        for (int j = 0; j < 2; j++) {
            float2 bhf[4], blf[4];
#pragma unroll
            for (int nf = 0; nf < 4; nf++) {
                int bi = (((wn * 4 + nf) * 2 + j) * 32 + lane) * 2;
                bhf[nf] = *(const float2*)&cur[4096 + bi];
                blf[nf] = *(const float2*)&cur[6144 + bi];
            }
#pragma unroll
            for (int mf = 0; mf < 4; mf++) {
                int ai = (((wm * 4 + mf) * 2 + j) * 32 + lane) * 4;
                float4 ah = *(const float4*)&cur[ai];
                float4 al = *(const float4*)&cur[2048 + ai];
#pragma unroll
                for (int nf = 0; nf < 4; nf++)
                    mma3_f(acc[mf][nf], ah, al, bhf[nf], blf[nf]);
            }
        }
    }

    // ---- epilogue: bias + split-scatter into fragment planes ----
    int gg = lane >> 2, tg = lane & 3;
    int row0 = blockIdx.x * 128, col0 = blockIdx.y * 128;
#pragma unroll
    for (int mf = 0; mf < 4; mf++) {
#pragma unroll
        for (int half = 0; half < 2; half++) {
            int t  = row0 + wm * 64 + mf * 16 + gg + half * 8;
            int b_ = t >> 9, s_ = t & 511;
#pragma unroll
            for (int nf = 0; nf < 4; nf++) {
#pragma unroll
                for (int c2 = 0; c2 < 2; c2++) {
                    int col = col0 + wn * 32 + nf * 8 + 2 * tg + c2;
                    int h_ = col >> 6, d = col & 63;
                    int bhx = b_ * HH + h_;
                    float val = acc[mf][nf][half * 2 + c2] + __ldg(&bias[col]);
                    float2 sp = tf32_split(val);
                    if (z == 0) {
                        size_t a = (((size_t)bhx * 32 + (s_ >> 4)) * 8 + (d >> 3)) * 128
                                 + ((s_ & 7) * 4 + (d & 3)) * 4
                                 + ((s_ >> 3) & 1) + 2 * ((d >> 2) & 1);
                        gQh[a] = sp.x; gQl[a] = sp.y;
                    } else if (z == 1) {
                        size_t a = (((size_t)bhx * 64 + (s_ >> 3)) * 8 + (d >> 3)) * 64
                                 + ((s_ & 7) * 4 + (d & 3)) * 2 + ((d >> 2) & 1);
                        gKh[a] = sp.x; gKl[a] = sp.y;
                    } else {
                        size_t a = (((size_t)bhx * 64 + (s_ >> 3)) * 8 + (d >> 3)) * 64
                                 + ((d & 7) * 4 + (s_ & 3)) * 2 + ((s_ >> 2) & 1);
                        gVh[a] = sp.x;        // hi only
                    }
                }
            }
        }
    }
}

// ============================================================
// Kernel 3: attention — 512 threads, q-tile 128; 3-stage
// pipelines (1 sync/chunk); row-max fused into QK epilogue;
// PV prep fuses normalize + probs write + frag pack; PV 1xTF32.
// QK stage 8192 fl: Kh[0,4096) Kl[4096,8192)
// PV stage 6144 fl: Ph[0,4096) Vh[4096,6144)
// ============================================================
#define QK_STG 8192
#define PV_STG 6144
#define BUF_FL (3 * QK_STG)       // 24576 (>= 3*PV_STG)
#define ATTN_SMEM ((BUF_FL + 512 + 128 + 128 + 256) * 4)   // ~102.4 KB

__global__ void __launch_bounds__(512, 1) attn_kernel(const int* __restrict__ mask,
                                                      float* __restrict__ out) {
    int qt = blockIdx.x, hh = blockIdx.y, bb = blockIdx.z;
    extern __shared__ float sm[];
    float* buf   = sm;                  // 3 stages
    float* msm   = sm + BUF_FL;         // 512
    float* smx   = msm + 512;           // 128 row maxes
    float* srinv = smx + 128;           // 128 row 1/sums
    float* smx2  = srinv + 128;         // 128 x 2 partial maxes

    int tid  = threadIdx.x;
    int warp = tid >> 5, lane = tid & 31;
    int g = lane >> 2, tig = lane & 3;
    int wq = warp >> 1, wk = warp & 1;   // wq 0..7, wk 0..1
    int bh = bb * HH + hh;
    float* ps = out + OUT_PROBS + ((size_t)bh * SS + (size_t)qt * 128) * SS;

    for (int i = tid; i < SS; i += 512)
        msm[i] = (1.0f - (float)mask[(size_t)bb * SS + i]) * -1250.0f;  // -1e4/8

    // Q fragments -> registers
    float4 qfh[8], qfl[8];
    {
        size_t qb = (((size_t)bh * 32 + qt * 8 + wq) * 8) * 128 + lane * 4;
#pragma unroll
        for (int kf = 0; kf < 8; kf++) {
            qfh[kf] = *(const float4*)&gQh[qb + kf * 128];
            qfl[kf] = *(const float4*)&gQl[qb + kf * 128];
        }
    }

    // ---- phase 1: QK^T (3-stage, 1 sync/chunk) + fused row max ----
    size_t kcb = (size_t)bh * 32768;
    auto copyK = [&](int st, int ch) {
        const float* sH = gKh + kcb + (size_t)ch * 4096;
        const float* sL = gKl + kcb + (size_t)ch * 4096;
        float* d = buf + st * QK_STG;
#pragma unroll
        for (int r = 0; r < 2; r++) {
            int off = (tid + r * 512) * 4;
            cp16(&d[off],        &sH[off]);
            cp16(&d[4096 + off], &sL[off]);
        }
    };
    copyK(0, 0); cp_commit();
    copyK(1, 1); cp_commit();

    float rmx0 = -INFINITY, rmx1 = -INFINITY;
    for (int ch = 0; ch < 8; ch++) {
        float* cur = buf + (ch % 3) * QK_STG;
        if (ch < 7) cp_wait1(); else cp_wait0();
        __syncthreads();
        if (ch + 2 < 8) { copyK((ch + 2) % 3, ch + 2); cp_commit(); }

        float acc[4][4] = {};
#pragma unroll
        for (int nf = 0; nf < 4; nf++) {
            int nl = wk * 4 + nf;
#pragma unroll
            for (int kf = 0; kf < 8; kf++) {
                float2 b2h = *(const float2*)&cur[((nl * 8 + kf) * 32 + lane) * 2];
                float2 b2l = *(const float2*)&cur[4096 + ((nl * 8 + kf) * 32 + lane) * 2];
                mma3_f(acc[nf], qfh[kf], qfl[kf], b2h, b2l);
            }
        }
#pragma unroll
        for (int nf = 0; nf < 4; nf++) {
            int key = ch * 64 + wk * 32 + nf * 8 + 2 * tig;
            float2 m2 = *(const float2*)&msm[key];
            int q0 = wq * 16 + g;
            float v0 = acc[nf][0] * m2.x, v1 = acc[nf][1] * m2.y;
            float v2 = acc[nf][2] * m2.x, v3 = acc[nf][3] * m2.y;
            rmx0 = fmaxf(rmx0, fmaxf(v0, v1));
            rmx1 = fmaxf(rmx1, fmaxf(v2, v3));
            *(float2*)&ps[(size_t)q0 * SS + key]       = make_float2(v0, v1);
            *(float2*)&ps[(size_t)(q0 + 8) * SS + key] = make_float2(v2, v3);
        }
    }
    // reduce max over tig lanes (quad) then across wk warps via smem
    rmx0 = fmaxf(rmx0, __shfl_xor_sync(~0u, rmx0, 1));
    rmx0 = fmaxf(rmx0, __shfl_xor_sync(~0u, rmx0, 2));
    rmx1 = fmaxf(rmx1, __shfl_xor_sync(~0u, rmx1, 1));
    rmx1 = fmaxf(rmx1, __shfl_xor_sync(~0u, rmx1, 2));
    if (tig == 0) {
        smx2[(wq * 16 + g) * 2 + wk]     = rmx0;
        smx2[(wq * 16 + g + 8) * 2 + wk] = rmx1;
    }
    __syncthreads();   // scores visible + smx2 ready

    // ---- phase 2: sum scan only (single strip pass) ----
    {
        int r = tid >> 2, l4 = tid & 3;
        const float* row = ps + (size_t)r * SS;
        float mx = fmaxf(smx2[r * 2], smx2[r * 2 + 1]);
        float sum = 0.f;
        for (int c = l4 * 4; c < SS; c += 16) {
            float4 s4 = *(const float4*)&row[c];
            sum += __expf(s4.x - mx) + __expf(s4.y - mx)
                 + __expf(s4.z - mx) + __expf(s4.w - mx);
        }
        sum += __shfl_xor_sync(~0u, sum, 1);
        sum += __shfl_xor_sync(~0u, sum, 2);
        if (l4 == 0) { smx[r] = mx; srinv[r] = 1.0f / sum; }
    }
    __syncthreads();

    // ---- phase 3: PV (3-stage). prep = normalize + probs write + pack ----
    size_t vcb = (size_t)bh * 32768;
    auto prepPV = [&](int st, int ch) {
        float* d = buf + st * PV_STG;
        const float* sV = gVh + vcb + (size_t)ch * 2048;
        cp16(&d[4096 + tid * 4], &sV[tid * 4]);
#pragma unroll
        for (int t = 0; t < 2; t++) {
            int idx = tid * 2 + t;
            int r  = idx >> 3;
            int c4 = (idx & 7) * 4;
            float* rowp = ps + (size_t)r * SS + ch * 32 + c4;
            float4 s4 = *(const float4*)rowp;
            float mx = smx[r], rv = srinv[r];
            float p[4];
            p[0] = __expf(s4.x - mx) * rv;
            p[1] = __expf(s4.y - mx) * rv;
            p[2] = __expf(s4.z - mx) * rv;
            p[3] = __expf(s4.w - mx) * rv;
            *(float4*)rowp = make_float4(p[0], p[1], p[2], p[3]);
            int qf = r >> 4, rr = r & 15;
            int e  = (rr >= 8 ? 1 : 0) + ((c4 & 4) ? 2 : 0);
            int sg = rr & 7;
            int base = (qf * 128 + (c4 >> 3) * 32 + sg * 4) * 4 + e;
#pragma unroll
            for (int j = 0; j < 4; j++) {
                int jj = (lane + j) & 3;
                d[base + jj * 4] = p[jj];
            }
        }
    };

    float acc2[4][4] = {};
    prepPV(0, 0); cp_commit();
    prepPV(1, 1); cp_commit();
    for (int ch = 0; ch < 16; ch++) {
        float* cur = buf + (ch % 3) * PV_STG;
        if (ch < 15) cp_wait1(); else cp_wait0();
        __syncthreads();
        if (ch + 2 < 16) { prepPV((ch + 2) % 3, ch + 2); cp_commit(); }
#pragma unroll
        for (int kf = 0; kf < 4; kf++) {
            float4 ah = *(const float4*)&cur[((wq * 4 + kf) * 32 + lane) * 4];
#pragma unroll
            for (int nf = 0; nf < 4; nf++) {
                int ng = wk * 4 + nf;
                float2 bv2 = *(const float2*)&cur[4096 + ((kf * 8 + ng) * 32 + lane) * 2];
                mma1_f(acc2[nf], ah, bv2);
            }
        }
    }

    // ---- epilogue: ctx (+ ctx0) ----
    int q0 = qt * 128 + wq * 16 + g;
#pragma unroll
    for (int nf = 0; nf < 4; nf++) {
        int dcol = hh * 64 + wk * 32 + nf * 8 + 2 * tig;
        size_t o0 = OUT_CTX + ((size_t)bb * SS + q0) * DD + dcol;
        size_t o1 = OUT_CTX + ((size_t)bb * SS + q0 + 8) * DD + dcol;
        *(float2*)&out[o0] = make_float2(acc2[nf][0], acc2[nf][1]);
        *(float2*)&out[o1] = make_float2(acc2[nf][2], acc2[nf][3]);
        if (q0 == 0)
            *(float2*)&out[(size_t)bb * DD + dcol] =
                make_float2(acc2[nf][0], acc2[nf][1]);
    }
}

// ============================================================
extern "C" void kernel_launch(void* const* d_in, const int* in_sizes, int n_in,
                              void* d_out, int out_size) {
    const int*   x_seq    = (const int*)  d_in[0];
    const int*   mask     = (const int*)  d_in[1];
    const float* word_emb = (const float*)d_in[2];
    const float* pos_emb  = (const float*)d_in[3];
    const float* ln_w     = (const float*)d_in[4];
    const float* ln_b     = (const float*)d_in[5];
    const float* wq       = (const float*)d_in[6];
    const float* bq       = (const float*)d_in[7];
    const float* wk       = (const float*)d_in[8];
    const float* bk       = (const float*)d_in[9];
    const float* wv       = (const float*)d_in[10];
    const float* bv       = (const float*)d_in[11];
    float* out = (float*)d_out;

    cudaFuncSetAttribute(embed_ln_kernel, cudaFuncAttributeMaxDynamicSharedMemorySize,
                         EMB_SMEM);
    embed_ln_kernel<<<TT / 16, 256, EMB_SMEM>>>(x_seq, word_emb, pos_emb, ln_w, ln_b);

    split_w_kernel<<<3 * 512 * 512 / 256, 256>>>(wq, wk, wv);

    cudaFuncSetAttribute(qkv_mma_kernel, cudaFuncAttributeMaxDynamicSharedMemorySize,
                         QKV_SMEM);
    dim3 ggrid(TT / 128, DD / 128, 3);
    qkv_mma_kernel<<<ggrid, 256, QKV_SMEM>>>(bq, bk, bv);

    cudaFuncSetAttribute(attn_kernel, cudaFuncAttributeMaxDynamicSharedMemorySize,
                         ATTN_SMEM);
    dim3 agrid(SS / 128, HH, BB);
    attn_kernel<<<agrid, 512, ATTN_SMEM>>>(mask, out);
}

// round 16
// speedup vs baseline: 1.0265x; 1.0265x over previous
#include <cuda_runtime.h>
#include <math.h>
#include <stdint.h>

#define BB 32
#define SS 512
#define DD 512
#define HH 8
#define DHH 64
#define TT (BB*SS)   // 16384 tokens
#define NBH (BB*HH)  // 256

// ---- scratch (__device__ globals; no dynamic alloc) ----
__device__ float g_ah[(size_t)1024 * 64 * 128];
__device__ float g_al[(size_t)1024 * 64 * 128];
__device__ float g_bh[3][(size_t)64 * 64 * 64];
__device__ float g_bl[3][(size_t)64 * 64 * 64];
// Q split A-frag planes: [bh(256)][qf(32)][kf(8)][lane(32)][e(4)]
__device__ float gQh[(size_t)NBH * 32 * 8 * 128];
__device__ float gQl[(size_t)NBH * 32 * 8 * 128];
// K split B-frag planes (n = key): [bh][nf(64)][kf(8)][lane(32)][e(2)]
__device__ float gKh[(size_t)NBH * 64 * 8 * 64];
__device__ float gKl[(size_t)NBH * 64 * 8 * 64];
// V hi-only B-frags (n = dh, k = key): [bh][kf(64)][nf(8)][lane(32)][e(2)]
__device__ float gVh[(size_t)NBH * 64 * 8 * 64];

// output layout: [ ctx0: B*D ][ ctx: B*S*D ][ probs: B*H*S*S ]
#define OUT_CTX   ((size_t)BB * DD)
#define OUT_PROBS (OUT_CTX + (size_t)BB * SS * DD)

// ============================================================
// tf32 split + mma helpers
// ============================================================
__device__ __forceinline__ float2 tf32_split(float x) {
    uint32_t hb;
    asm("cvt.rna.tf32.f32 %0, %1;" : "=r"(hb) : "f"(x));
    float hf = __uint_as_float(hb);
    float lo = x - hf;
    uint32_t lb;
    asm("cvt.rna.tf32.f32 %0, %1;" : "=r"(lb) : "f"(lo));
    return make_float2(hf, __uint_as_float(lb));
}

__device__ __forceinline__ void mma_tf32(float* c,
        uint32_t a0, uint32_t a1, uint32_t a2, uint32_t a3,
        uint32_t b0, uint32_t b1) {
    asm("mma.sync.aligned.m16n8k8.row.col.f32.tf32.tf32.f32 "
        "{%0,%1,%2,%3}, {%4,%5,%6,%7}, {%8,%9}, {%0,%1,%2,%3};"
        : "+f"(c[0]), "+f"(c[1]), "+f"(c[2]), "+f"(c[3])
        : "r"(a0), "r"(a1), "r"(a2), "r"(a3), "r"(b0), "r"(b1));
}

__device__ __forceinline__ void mma3_f(float* c, float4 ah, float4 al,
                                       float2 bhv, float2 blv) {
    uint32_t a0 = __float_as_uint(ah.x), a1 = __float_as_uint(ah.y);
    uint32_t a2 = __float_as_uint(ah.z), a3 = __float_as_uint(ah.w);
    uint32_t l0 = __float_as_uint(al.x), l1 = __float_as_uint(al.y);
    uint32_t l2 = __float_as_uint(al.z), l3 = __float_as_uint(al.w);
    uint32_t b0 = __float_as_uint(bhv.x), b1 = __float_as_uint(bhv.y);
    uint32_t c0 = __float_as_uint(blv.x), c1 = __float_as_uint(blv.y);
    mma_tf32(c, a0, a1, a2, a3, b0, b1);
    mma_tf32(c, a0, a1, a2, a3, c0, c1);
    mma_tf32(c, l0, l1, l2, l3, b0, b1);
}

// 1xTF32: c += Ah*Bh
__device__ __forceinline__ void mma1_f(float* c, float4 ah, float2 bhv) {
    mma_tf32(c, __float_as_uint(ah.x), __float_as_uint(ah.y),
                __float_as_uint(ah.z), __float_as_uint(ah.w),
                __float_as_uint(bhv.x), __float_as_uint(bhv.y));
}

__device__ __forceinline__ void cp16(float* smem_dst, const float* gsrc) {
    uint32_t s = (uint32_t)__cvta_generic_to_shared(smem_dst);
    asm volatile("cp.async.ca.shared.global [%0], [%1], 16;" :: "r"(s), "l"(gsrc));
}
__device__ __forceinline__ void cp_commit() {
    asm volatile("cp.async.commit_group;");
}
__device__ __forceinline__ void cp_wait1() {
    asm volatile("cp.async.wait_group 1;");
}
__device__ __forceinline__ void cp_wait0() {
    asm volatile("cp.async.wait_group 0;");
}

// ============================================================
// Kernel 1: embed + pos + LayerNorm -> split tiled h planes
// ============================================================
#define EMB_SMEM (2 * 16 * 512 * 4)

__global__ void __launch_bounds__(256) embed_ln_kernel(
        const int* __restrict__ x_seq,
        const float* __restrict__ word_emb,
        const float* __restrict__ pos_emb,
        const float* __restrict__ ln_w,
        const float* __restrict__ ln_b) {
    extern __shared__ float es[];
    float* shi = es;
    float* slo = es + 8192;

    int rb   = blockIdx.x;
    int tid  = threadIdx.x;
    int w    = tid >> 5, lane = tid & 31;
    int rloc = 2 * w + (lane >> 4);
    int li   = lane & 15;
    int row  = rb * 16 + rloc;
    int s    = row & (SS - 1);
    int x    = x_seq[row];
    const float* we = word_emb + (size_t)x * DD;
    const float* pe = pos_emb  + (size_t)s * DD;

    float v[32];
    float sum = 0.f;
#pragma unroll
    for (int q = 0; q < 8; q++) {
        int c = li * 32 + q * 4;
        float4 a = *(const float4*)&we[c];
        float4 b = *(const float4*)&pe[c];
        v[q*4+0] = a.x + b.x; v[q*4+1] = a.y + b.y;
        v[q*4+2] = a.z + b.z; v[q*4+3] = a.w + b.w;
        sum += v[q*4+0] + v[q*4+1] + v[q*4+2] + v[q*4+3];
    }
#pragma unroll
    for (int o = 8; o > 0; o >>= 1) sum += __shfl_xor_sync(~0u, sum, o);
    float mu = sum * (1.0f / DD);
    float sq = 0.f;
#pragma unroll
    for (int q = 0; q < 32; q++) { float d = v[q] - mu; sq += d * d; }
#pragma unroll
    for (int o = 8; o > 0; o >>= 1) sq += __shfl_xor_sync(~0u, sq, o);
    float rstd = rsqrtf(sq * (1.0f / DD) + 1e-5f);

    int g  = rloc & 7, hh_ = rloc >> 3;
#pragma unroll
    for (int q = 0; q < 32; q++) {
        int c = li * 32 + q;
        float o = (v[q] - mu) * rstd * ln_w[c] + ln_b[c];
        float2 sp = tf32_split(o);
        int kb = c >> 3, tig = c & 3, ch = (c >> 2) & 1;
        int ta = (kb * 32 + g * 4 + tig) * 4 + hh_ + 2 * ch;
        shi[ta] = sp.x;
        slo[ta] = sp.y;
    }
    __syncthreads();
    size_t base = (size_t)rb * 8192;
#pragma unroll
    for (int r = 0; r < 8; r++) {
        int i = (tid + r * 256) * 4;
        *(float4*)&g_ah[base + i] = *(const float4*)&shi[i];
        *(float4*)&g_al[base + i] = *(const float4*)&slo[i];
    }
}

// ============================================================
// Kernel 1b: split+tile weights (one-shot)
// ============================================================
__global__ void split_w_kernel(const float* __restrict__ wq,
                               const float* __restrict__ wk,
                               const float* __restrict__ wv) {
    int idx = blockIdx.x * 256 + threadIdx.x;
    int z = idx >> 18;
    int rem = idx & ((1 << 18) - 1);
    int n = rem >> 9, k = rem & 511;
    const float* W = (z == 0) ? wq : (z == 1) ? wk : wv;
    float2 sp = tf32_split(W[(size_t)n * DD + k]);
    int cb = n >> 3, kb = k >> 3, g = n & 7, tig = k & 3, e = (k >> 2) & 1;
    size_t a = ((size_t)(cb * 64 + kb) * 32 + g * 4 + tig) * 2 + e;
    g_bh[z][a] = sp.x;
    g_bl[z][a] = sp.y;
}

// ============================================================
// Kernel 2: QKV GEMM — 2-stage cp.async (R13 validated config)
// ============================================================
#define QKV_SMEM (2 * 8192 * 4)

__global__ void __launch_bounds__(256, 2) qkv_mma_kernel(
        const float* __restrict__ bq, const float* __restrict__ bk,
        const float* __restrict__ bv) {
    const float* bias;
    int z = blockIdx.z;
    bias = (z == 0) ? bq : (z == 1) ? bk : bv;
    const float* Bh = g_bh[z];
    const float* Bl = g_bl[z];

    extern __shared__ float smem[];
    int tid  = threadIdx.x;
    int warp = tid >> 5, lane = tid & 31;
    int wm = warp & 1, wn = warp >> 1;
    int rb0 = blockIdx.x * 8;
    int cb0 = blockIdx.y * 16;

    float acc[4][4][4] = {};

    auto copy_chunk = [&](float* st, int kc) {
#pragma unroll
        for (int r = 0; r < 2; r++) {
            int f = (tid + r * 256) * 4;
            int i = f >> 8, j = (f >> 7) & 1, t = f & 127;
            size_t src = ((size_t)(rb0 + i) * 64 + kc * 2 + j) * 128 + t;
            cp16(&st[f],        &g_ah[src]);
            cp16(&st[2048 + f], &g_al[src]);
        }
#pragma unroll
        for (int r = 0; r < 2; r++) {
            int f = (tid + r * 256) * 4;
            int i = f >> 7, j = (f >> 6) & 1, t = f & 63;
            size_t src = ((size_t)(cb0 + i) * 64 + kc * 2 + j) * 64 + t;
            cp16(&st[4096 + f], &Bh[src]);
            cp16(&st[6144 + f], &Bl[src]);
        }
    };

    copy_chunk(smem, 0);
    cp_commit();

    for (int kc = 0; kc < 32; kc++) {
        float* cur = smem + (kc & 1) * 8192;
        if (kc < 31) {
            copy_chunk(smem + ((kc + 1) & 1) * 8192, kc + 1);
            cp_commit();
            cp_wait1();
        } else {
            cp_wait0();
        }
        __syncthreads();

#pragma unroll
        for (int j = 0; j < 2; j++) {
            float2 bhf[4], blf[4];
#pragma unroll
            for (int nf = 0; nf < 4; nf++) {
                int bi = (((wn * 4 + nf) * 2 + j) * 32 + lane) * 2;
                bhf[nf] = *(const float2*)&cur[4096 + bi];
                blf[nf] = *(const float2*)&cur[6144 + bi];
            }
#pragma unroll
            for (int mf = 0; mf < 4; mf++) {
                int ai = (((wm * 4 + mf) * 2 + j) * 32 + lane) * 4;
                float4 ah = *(const float4*)&cur[ai];
                float4 al = *(const float4*)&cur[2048 + ai];
#pragma unroll
                for (int nf = 0; nf < 4; nf++)
                    mma3_f(acc[mf][nf], ah, al, bhf[nf], blf[nf]);
            }
        }
        __syncthreads();
    }

    // ---- epilogue: bias + split-scatter into fragment planes ----
    int gg = lane >> 2, tg = lane & 3;
    int row0 = blockIdx.x * 128, col0 = blockIdx.y * 128;
#pragma unroll
    for (int mf = 0; mf < 4; mf++) {
#pragma unroll
        for (int half = 0; half < 2; half++) {
            int t  = row0 + wm * 64 + mf * 16 + gg + half * 8;
            int b_ = t >> 9, s_ = t & 511;
#pragma unroll
            for (int nf = 0; nf < 4; nf++) {
#pragma unroll
                for (int c2 = 0; c2 < 2; c2++) {
                    int col = col0 + wn * 32 + nf * 8 + 2 * tg + c2;
                    int h_ = col >> 6, d = col & 63;
                    int bhx = b_ * HH + h_;
                    float val = acc[mf][nf][half * 2 + c2] + __ldg(&bias[col]);
                    float2 sp = tf32_split(val);
                    if (z == 0) {
                        size_t a = (((size_t)bhx * 32 + (s_ >> 4)) * 8 + (d >> 3)) * 128
                                 + ((s_ & 7) * 4 + (d & 3)) * 4
                                 + ((s_ >> 3) & 1) + 2 * ((d >> 2) & 1);
                        gQh[a] = sp.x; gQl[a] = sp.y;
                    } else if (z == 1) {
                        size_t a = (((size_t)bhx * 64 + (s_ >> 3)) * 8 + (d >> 3)) * 64
                                 + ((s_ & 7) * 4 + (d & 3)) * 2 + ((d >> 2) & 1);
                        gKh[a] = sp.x; gKl[a] = sp.y;
                    } else {
                        size_t a = (((size_t)bhx * 64 + (s_ >> 3)) * 8 + (d >> 3)) * 64
                                 + ((d & 7) * 4 + (s_ & 3)) * 2 + ((s_ >> 2) & 1);
                        gVh[a] = sp.x;        // hi only
                    }
                }
            }
        }
    }
}

// ============================================================
// Kernel 3: attention — R14 validated config: 512 threads,
// q-tile 128, 3-stage pipelines (1 sync/chunk), fused row-max,
// PV prep fuses normalize + probs write + frag pack; PV 1xTF32.
// ============================================================
#define QK_STG 8192
#define PV_STG 6144
#define BUF_FL (3 * QK_STG)
#define ATTN_SMEM ((BUF_FL + 512 + 128 + 128 + 256) * 4)

__global__ void __launch_bounds__(512, 1) attn_kernel(const int* __restrict__ mask,
                                                      float* __restrict__ out) {
    int qt = blockIdx.x, hh = blockIdx.y, bb = blockIdx.z;
    extern __shared__ float sm[];
    float* buf   = sm;
    float* msm   = sm + BUF_FL;
    float* smx   = msm + 512;
    float* srinv = smx + 128;
    float* smx2  = srinv + 128;

    int tid  = threadIdx.x;
    int warp = tid >> 5, lane = tid & 31;
    int g = lane >> 2, tig = lane & 3;
    int wq = warp >> 1, wk = warp & 1;
    int bh = bb * HH + hh;
    float* ps = out + OUT_PROBS + ((size_t)bh * SS + (size_t)qt * 128) * SS;

    for (int i = tid; i < SS; i += 512)
        msm[i] = (1.0f - (float)mask[(size_t)bb * SS + i]) * -1250.0f;  // -1e4/8

    float4 qfh[8], qfl[8];
    {
        size_t qb = (((size_t)bh * 32 + qt * 8 + wq) * 8) * 128 + lane * 4;
#pragma unroll
        for (int kf = 0; kf < 8; kf++) {
            qfh[kf] = *(const float4*)&gQh[qb + kf * 128];
            qfl[kf] = *(const float4*)&gQl[qb + kf * 128];
        }
    }

    // ---- phase 1: QK^T (3-stage, 1 sync/chunk) + fused row max ----
    size_t kcb = (size_t)bh * 32768;
    auto copyK = [&](int st, int ch) {
        const float* sH = gKh + kcb + (size_t)ch * 4096;
        const float* sL = gKl + kcb + (size_t)ch * 4096;
        float* d = buf + st * QK_STG;
#pragma unroll
        for (int r = 0; r < 2; r++) {
            int off = (tid + r * 512) * 4;
            cp16(&d[off],        &sH[off]);
            cp16(&d[4096 + off], &sL[off]);
        }
    };
    copyK(0, 0); cp_commit();
    copyK(1, 1); cp_commit();

    float rmx0 = -INFINITY, rmx1 = -INFINITY;
    for (int ch = 0; ch < 8; ch++) {
        float* cur = buf + (ch % 3) * QK_STG;
        if (ch < 7) cp_wait1(); else cp_wait0();
        __syncthreads();
        if (ch + 2 < 8) { copyK((ch + 2) % 3, ch + 2); cp_commit(); }

        float acc[4][4] = {};
#pragma unroll
        for (int nf = 0; nf < 4; nf++) {
            int nl = wk * 4 + nf;
#pragma unroll
            for (int kf = 0; kf < 8; kf++) {
                float2 b2h = *(const float2*)&cur[((nl * 8 + kf) * 32 + lane) * 2];
                float2 b2l = *(const float2*)&cur[4096 + ((nl * 8 + kf) * 32 + lane) * 2];
                mma3_f(acc[nf], qfh[kf], qfl[kf], b2h, b2l);
            }
        }
#pragma unroll
        for (int nf = 0; nf < 4; nf++) {
            int key = ch * 64 + wk * 32 + nf * 8 + 2 * tig;
            float2 m2 = *(const float2*)&msm[key];
            int q0 = wq * 16 + g;
            float v0 = acc[nf][0] * m2.x, v1 = acc[nf][1] * m2.y;
            float v2 = acc[nf][2] * m2.x, v3 = acc[nf][3] * m2.y;
            rmx0 = fmaxf(rmx0, fmaxf(v0, v1));
            rmx1 = fmaxf(rmx1, fmaxf(v2, v3));
            *(float2*)&ps[(size_t)q0 * SS + key]       = make_float2(v0, v1);
            *(float2*)&ps[(size_t)(q0 + 8) * SS + key] = make_float2(v2, v3);
        }
    }
    rmx0 = fmaxf(rmx0, __shfl_xor_sync(~0u, rmx0, 1));
    rmx0 = fmaxf(rmx0, __shfl_xor_sync(~0u, rmx0, 2));
    rmx1 = fmaxf(rmx1, __shfl_xor_sync(~0u, rmx1, 1));
    rmx1 = fmaxf(rmx1, __shfl_xor_sync(~0u, rmx1, 2));
    if (tig == 0) {
        smx2[(wq * 16 + g) * 2 + wk]     = rmx0;
        smx2[(wq * 16 + g + 8) * 2 + wk] = rmx1;
    }
    __syncthreads();

    // ---- phase 2: sum scan only ----
    {
        int r = tid >> 2, l4 = tid & 3;
        const float* row = ps + (size_t)r * SS;
        float mx = fmaxf(smx2[r * 2], smx2[r * 2 + 1]);
        float sum = 0.f;
        for (int c = l4 * 4; c < SS; c += 16) {
            float4 s4 = *(const float4*)&row[c];
            sum += __expf(s4.x - mx) + __expf(s4.y - mx)
                 + __expf(s4.z - mx) + __expf(s4.w - mx);
        }
        sum += __shfl_xor_sync(~0u, sum, 1);
        sum += __shfl_xor_sync(~0u, sum, 2);
        if (l4 == 0) { smx[r] = mx; srinv[r] = 1.0f / sum; }
    }
    __syncthreads();

    // ---- phase 3: PV (3-stage) ----
    size_t vcb = (size_t)bh * 32768;
    auto prepPV = [&](int st, int ch) {
        float* d = buf + st * PV_STG;
        const float* sV = gVh + vcb + (size_t)ch * 2048;
        cp16(&d[4096 + tid * 4], &sV[tid * 4]);
#pragma unroll
        for (int t = 0; t < 2; t++) {
            int idx = tid * 2 + t;
            int r  = idx >> 3;
            int c4 = (idx & 7) * 4;
            float* rowp = ps + (size_t)r * SS + ch * 32 + c4;
            float4 s4 = *(const float4*)rowp;
            float mx = smx[r], rv = srinv[r];
            float p[4];
            p[0] = __expf(s4.x - mx) * rv;
            p[1] = __expf(s4.y - mx) * rv;
            p[2] = __expf(s4.z - mx) * rv;
            p[3] = __expf(s4.w - mx) * rv;
            *(float4*)rowp = make_float4(p[0], p[1], p[2], p[3]);
            int qf = r >> 4, rr = r & 15;
            int e  = (rr >= 8 ? 1 : 0) + ((c4 & 4) ? 2 : 0);
            int sg = rr & 7;
            int base = (qf * 128 + (c4 >> 3) * 32 + sg * 4) * 4 + e;
#pragma unroll
            for (int j = 0; j < 4; j++) {
                int jj = (lane + j) & 3;
                d[base + jj * 4] = p[jj];
            }
        }
    };

    float acc2[4][4] = {};
    prepPV(0, 0); cp_commit();
    prepPV(1, 1); cp_commit();
    for (int ch = 0; ch < 16; ch++) {
        float* cur = buf + (ch % 3) * PV_STG;
        if (ch < 15) cp_wait1(); else cp_wait0();
        __syncthreads();
        if (ch + 2 < 16) { prepPV((ch + 2) % 3, ch + 2); cp_commit(); }
#pragma unroll
        for (int kf = 0; kf < 4; kf++) {
            float4 ah = *(const float4*)&cur[((wq * 4 + kf) * 32 + lane) * 4];
#pragma unroll
            for (int nf = 0; nf < 4; nf++) {
                int ng = wk * 4 + nf;
                float2 bv2 = *(const float2*)&cur[4096 + ((kf * 8 + ng) * 32 + lane) * 2];
                mma1_f(acc2[nf], ah, bv2);
            }
        }
    }

    // ---- epilogue: ctx (+ ctx0) ----
    int q0 = qt * 128 + wq * 16 + g;
#pragma unroll
    for (int nf = 0; nf < 4; nf++) {
        int dcol = hh * 64 + wk * 32 + nf * 8 + 2 * tig;
        size_t o0 = OUT_CTX + ((size_t)bb * SS + q0) * DD + dcol;
        size_t o1 = OUT_CTX + ((size_t)bb * SS + q0 + 8) * DD + dcol;
        *(float2*)&out[o0] = make_float2(acc2[nf][0], acc2[nf][1]);
        *(float2*)&out[o1] = make_float2(acc2[nf][2], acc2[nf][3]);
        if (q0 == 0)
            *(float2*)&out[(size_t)bb * DD + dcol] =
                make_float2(acc2[nf][0], acc2[nf][1]);
    }
}

// ============================================================
extern "C" void kernel_launch(void* const* d_in, const int* in_sizes, int n_in,
                              void* d_out, int out_size) {
    const int*   x_seq    = (const int*)  d_in[0];
    const int*   mask     = (const int*)  d_in[1];
    const float* word_emb = (const float*)d_in[2];
    const float* pos_emb  = (const float*)d_in[3];
    const float* ln_w     = (const float*)d_in[4];
    const float* ln_b     = (const float*)d_in[5];
    const float* wq       = (const float*)d_in[6];
    const float* bq       = (const float*)d_in[7];
    const float* wk       = (const float*)d_in[8];
    const float* bk       = (const float*)d_in[9];
    const float* wv       = (const float*)d_in[10];
    const float* bv       = (const float*)d_in[11];
    float* out = (float*)d_out;

    cudaFuncSetAttribute(embed_ln_kernel, cudaFuncAttributeMaxDynamicSharedMemorySize,
                         EMB_SMEM);
    embed_ln_kernel<<<TT / 16, 256, EMB_SMEM>>>(x_seq, word_emb, pos_emb, ln_w, ln_b);

    split_w_kernel<<<3 * 512 * 512 / 256, 256>>>(wq, wk, wv);

    cudaFuncSetAttribute(qkv_mma_kernel, cudaFuncAttributeMaxDynamicSharedMemorySize,
                         QKV_SMEM);
    dim3 ggrid(TT / 128, DD / 128, 3);
    qkv_mma_kernel<<<ggrid, 256, QKV_SMEM>>>(bq, bk, bv);

    cudaFuncSetAttribute(attn_kernel, cudaFuncAttributeMaxDynamicSharedMemorySize,
                         ATTN_SMEM);
    dim3 agrid(SS / 128, HH, BB);
    attn_kernel<<<agrid, 512, ATTN_SMEM>>>(mask, out);
}